// round 1
// baseline (speedup 1.0000x reference)
#include <cuda_runtime.h>
#include <cuda_fp16.h>

// Problem constants (fixed by the reference):
//   x:   (B=4, 3, H=2048, W=2048) fp32
//   LUT: (3, 33, 33, 33) fp32, index = c*33^3 + b*1089 + g*33 + r
#define DIML   33
#define NPTS   35937            // 33^3
#define HW     4194304          // 2048*2048 (plane size)
#define HW4    1048576          // HW/4  (= 2^20)
#define NVEC   4194304          // B*HW/4 total float4 pixel-vecs
#define THREADS 512
#define BLOCKS  152             // one block per SM (GB300 = 152 SMs), 1 wave
#define SMEM_BYTES (NPTS * 4 + NPTS * 2 + 16)   // half2 rg table + half b table

struct F3 { float x, y, z; };

__device__ __forceinline__ F3 lerp3(F3 a, F3 b, float f) {
    F3 r;
    r.x = fmaf(f, b.x - a.x, a.x);
    r.y = fmaf(f, b.y - a.y, a.y);
    r.z = fmaf(f, b.z - a.z, a.z);
    return r;
}

__device__ __forceinline__ F3 load3(const __half2* __restrict__ srg,
                                    const __half*  __restrict__ sb, int i) {
    float2 rg = __half22float2(srg[i]);
    F3 v;
    v.x = rg.x;
    v.y = rg.y;
    v.z = __half2float(sb[i]);
    return v;
}

__device__ __forceinline__ void lut_px(float r, float g, float b,
                                       const __half2* __restrict__ srg,
                                       const __half*  __restrict__ sb,
                                       float& outr, float& outg, float& outb) {
    float rr = r * 32.0f;
    float gg = g * 32.0f;
    float bb = b * 32.0f;
    int r0 = __float2int_rd(rr);
    int g0 = __float2int_rd(gg);
    int b0 = __float2int_rd(bb);
    r0 = min(max(r0, 0), 31);
    g0 = min(max(g0, 0), 31);
    b0 = min(max(b0, 0), 31);
    float fr = rr - (float)r0;
    float fg = gg - (float)g0;
    float fb = bb - (float)b0;

    int i000 = b0 * 1089 + g0 * 33 + r0;
    int i010 = i000 + 33;
    int i100 = i000 + 1089;
    int i110 = i100 + 33;

    F3 v000 = load3(srg, sb, i000);
    F3 v001 = load3(srg, sb, i000 + 1);
    F3 v010 = load3(srg, sb, i010);
    F3 v011 = load3(srg, sb, i010 + 1);
    F3 v100 = load3(srg, sb, i100);
    F3 v101 = load3(srg, sb, i100 + 1);
    F3 v110 = load3(srg, sb, i110);
    F3 v111 = load3(srg, sb, i110 + 1);

    F3 c00 = lerp3(v000, v001, fr);
    F3 c01 = lerp3(v010, v011, fr);
    F3 c10 = lerp3(v100, v101, fr);
    F3 c11 = lerp3(v110, v111, fr);
    F3 c0  = lerp3(c00, c01, fg);
    F3 c1  = lerp3(c10, c11, fg);
    F3 c   = lerp3(c0, c1, fb);

    outr = c.x;
    outg = c.y;
    outb = c.z;
}

extern __shared__ unsigned char smem_raw[];

__global__ void __launch_bounds__(THREADS, 1)
lut3d_kernel(const float* __restrict__ x, const float* __restrict__ LUT,
             float* __restrict__ out) {
    __half2* srg = (__half2*)smem_raw;
    __half*  sb  = (__half*)(smem_raw + (size_t)NPTS * sizeof(__half2));

    // Cooperative fp32 -> fp16 LUT conversion into shared memory.
    for (int i = threadIdx.x; i < NPTS; i += THREADS) {
        float vr = __ldg(&LUT[i]);
        float vg = __ldg(&LUT[NPTS + i]);
        float vb = __ldg(&LUT[2 * NPTS + i]);
        srg[i] = __floats2half2_rn(vr, vg);
        sb[i]  = __float2half_rn(vb);
    }
    __syncthreads();

    const float4* __restrict__ x4 = (const float4*)x;
    float4* __restrict__ o4 = (float4*)out;

    const int stride = gridDim.x * blockDim.x;
    for (int v = blockIdx.x * blockDim.x + threadIdx.x; v < NVEC; v += stride) {
        int img  = v >> 20;            // v / HW4
        int iv   = v & (HW4 - 1);      // v % HW4
        int base = img * (3 * HW4) + iv;

        float4 pr = x4[base];
        float4 pg = x4[base + HW4];
        float4 pb = x4[base + 2 * HW4];

        float4 orr, org, orb;
        lut_px(pr.x, pg.x, pb.x, srg, sb, orr.x, org.x, orb.x);
        lut_px(pr.y, pg.y, pb.y, srg, sb, orr.y, org.y, orb.y);
        lut_px(pr.z, pg.z, pb.z, srg, sb, orr.z, org.z, orb.z);
        lut_px(pr.w, pg.w, pb.w, srg, sb, orr.w, org.w, orb.w);

        o4[base]           = orr;
        o4[base + HW4]     = org;
        o4[base + 2 * HW4] = orb;
    }
}

extern "C" void kernel_launch(void* const* d_in, const int* in_sizes, int n_in,
                              void* d_out, int out_size) {
    const float* x   = (const float*)d_in[0];
    const float* LUT = (const float*)d_in[1];
    float* out = (float*)d_out;

    cudaFuncSetAttribute(lut3d_kernel,
                         cudaFuncAttributeMaxDynamicSharedMemorySize, SMEM_BYTES);
    lut3d_kernel<<<BLOCKS, THREADS, SMEM_BYTES>>>(x, LUT, out);
}